// round 2
// baseline (speedup 1.0000x reference)
#include <cuda_runtime.h>
#include <cuda_fp16.h>
#include <cstdint>

// Problem constants
#define B_  32
#define N_  4096
#define E_  8192
#define D_  128
#define ROWS_TOTAL (B_*N_)        // 131072
#define NEDGE (B_*E_)             // 262144

// ---------------- device-global scratch (no runtime allocation allowed) ---------
__device__ float  g_agg[B_*N_*D_];         // 64MB aggregation buffer
__device__ __half g_wt[2*384*128];         // transposed fp16 weights: [mat][col(384)][k(128)]

// ---------------- smem layout (bytes) -------------------------------------------
// A tiles: fp16 [128 rows][136 halves] (8-half pad -> 272B row stride, ldmatrix
// conflict-free: consecutive rows shift by 4 banks).
#define OFF_BIAS  0                 // 768 floats
#define OFF_AG    3072              // agg fp16 tile   (34816 B)
#define OFF_AH    37888             // h   fp16 tile   (34816 B)
#define OFF_BX    72704             // Wx gate slice   (34816 B)
#define OFF_BH    107520            // Wh gate slice   (34816 B)
#define OFF_HF    142336            // exact fp32 h [128][132] (67584 B)
#define SMEM_TOTAL 209920

__device__ __forceinline__ uint32_t smem_u32(const void* p) {
    uint32_t a;
    asm("{ .reg .u64 t; cvta.to.shared.u64 t, %1; cvt.u32.u64 %0, t; }" : "=r"(a) : "l"(p));
    return a;
}

__device__ __forceinline__ void ldsm4(uint32_t d[4], uint32_t addr) {
    asm volatile("ldmatrix.sync.aligned.m8n8.x4.shared.b16 {%0,%1,%2,%3}, [%4];"
                 : "=r"(d[0]), "=r"(d[1]), "=r"(d[2]), "=r"(d[3]) : "r"(addr));
}

__device__ __forceinline__ void mma_16816(float c[4], const uint32_t a[4], uint32_t b0, uint32_t b1) {
    asm volatile(
        "mma.sync.aligned.m16n8k16.row.col.f32.f16.f16.f32 "
        "{%0,%1,%2,%3}, {%4,%5,%6,%7}, {%8,%9}, {%0,%1,%2,%3};"
        : "+f"(c[0]), "+f"(c[1]), "+f"(c[2]), "+f"(c[3])
        : "r"(a[0]), "r"(a[1]), "r"(a[2]), "r"(a[3]), "r"(b0), "r"(b1));
}

// ================================================================================
// Kernel 1: transpose + fp16-convert weights:  g_wt[mat][col][k] = W[k*384+col]
// ================================================================================
__global__ void prep_w_kernel(const float* __restrict__ kern, const float* __restrict__ rker) {
    int i = blockIdx.x * blockDim.x + threadIdx.x;
    if (i >= 2 * 384 * 128) return;
    int mat = i / (384 * 128);
    int rem = i - mat * (384 * 128);
    int col = rem >> 7;
    int k   = rem & 127;
    const float* W = mat ? rker : kern;
    g_wt[i] = __float2half_rn(W[k * 384 + col]);
}

// ================================================================================
// Kernel 2: zero the aggregation scratch
// ================================================================================
__global__ void zero_agg_kernel() {
    const float4 z = make_float4(0.f, 0.f, 0.f, 0.f);
    int n4 = (B_ * N_ * D_) / 4;
    for (int i = blockIdx.x * blockDim.x + threadIdx.x; i < n4; i += gridDim.x * blockDim.x)
        reinterpret_cast<float4*>(g_agg)[i] = z;
}

// ================================================================================
// Kernel 3: scatter-add messages into g_agg.  One warp per edge.
// ================================================================================
__global__ void scatter_kernel(const float* __restrict__ msgs, const int* __restrict__ conn) {
    int gwarp = (blockIdx.x * blockDim.x + threadIdx.x) >> 5;
    int lane  = threadIdx.x & 31;
    if (gwarp >= NEDGE) return;
    int b = gwarp >> 13;                                  // / E_
    int tgt;
    if (lane == 0) tgt = conn[gwarp * 2 + 1];
    tgt = __shfl_sync(0xffffffffu, tgt, 0);
    float4 m = reinterpret_cast<const float4*>(msgs)[gwarp * 32 + lane];
    float* dst = g_agg + ((size_t)((b << 12) + tgt)) * 128 + lane * 4;
    atomicAdd(dst + 0, m.x);
    atomicAdd(dst + 1, m.y);
    atomicAdd(dst + 2, m.z);
    atomicAdd(dst + 3, m.w);
}

// ================================================================================
// Kernel 4: fused dual-GEMM (mma.sync f16) + GRU epilogue.
// 1024 CTAs x 128 rows, 256 threads (8 warps x 16 rows).
// ================================================================================

// Stage one gate's W slices (both mats) into smem, fp16 [128 n][136 k-halves].
__device__ __forceinline__ void stage_B(char* smem, int g, int tid) {
    for (int idx = tid; idx < 4096; idx += 256) {
        int mat = idx >> 11;
        int rem = idx & 2047;
        int n   = rem >> 4;
        int seg = rem & 15;     // 8 halves per seg
        uint4 v = reinterpret_cast<const uint4*>(
            g_wt + (size_t)(mat * 384 + g * 128 + n) * 128)[seg];
        *reinterpret_cast<uint4*>(smem + (mat ? OFF_BH : OFF_BX) + n * 272 + seg * 16) = v;
    }
}

// acc[n][j] += A(16x128) @ B(128x128)^T  for this warp's 16 rows.
// aBase/bBase are smem addresses pre-offset with the per-lane ldmatrix pattern.
__device__ __forceinline__ void gemm_into(float (&acc)[16][4], uint32_t aBase, uint32_t bBase) {
#pragma unroll
    for (int ks2 = 0; ks2 < 4; ks2++) {              // 32 k-cols per iter
        uint32_t aA[4], aB[4];
        ldsm4(aA, aBase + ks2 * 64);                 // k0   .. k0+15
        ldsm4(aB, aBase + ks2 * 64 + 32);            // k0+16.. k0+31
#pragma unroll
        for (int n = 0; n < 16; n++) {
            uint32_t b[4];
            ldsm4(b, bBase + n * 2176 + ks2 * 64);   // 4 k-chunks of this n-tile
            mma_16816(acc[n], aA, b[0], b[1]);
            mma_16816(acc[n], aB, b[2], b[3]);
        }
    }
}

__global__ void __launch_bounds__(256, 1)
gru_gemm_kernel(const float* __restrict__ atom_state,
                const float* __restrict__ bias,
                float* __restrict__ out)
{
    extern __shared__ char smem[];
    const uint32_t sb = smem_u32(smem);
    const int tid  = threadIdx.x;
    const int wid  = tid >> 5;
    const int lane = tid & 31;
    const int row0 = blockIdx.x * 128;

    float* bias_s = reinterpret_cast<float*>(smem + OFF_BIAS);
    float* hf_s   = reinterpret_cast<float*>(smem + OFF_HF);

    // ---- stage bias ----
    for (int i = tid; i < 768; i += 256) bias_s[i] = bias[i];

    // ---- stage A tiles: fp32 -> fp16 padded rows; exact fp32 copy of h ----
    const float4* aggp = reinterpret_cast<const float4*>(g_agg + (size_t)row0 * 128);
    const float4* hp   = reinterpret_cast<const float4*>(atom_state + (size_t)row0 * 128);
    for (int idx = tid; idx < 2 * 128 * 32; idx += 256) {
        int src = idx >> 12;              // 0: agg, 1: h
        int rem = idx & 4095;
        int row = rem >> 5;
        int f4  = rem & 31;
        float4 v = src ? hp[rem] : aggp[rem];
        union { __half2 h2[2]; uint2 u; } cv;
        cv.h2[0] = __floats2half2_rn(v.x, v.y);
        cv.h2[1] = __floats2half2_rn(v.z, v.w);
        *reinterpret_cast<uint2*>(smem + (src ? OFF_AH : OFF_AG) + row * 272 + f4 * 8) = cv.u;
        if (src)
            *reinterpret_cast<float4*>(hf_s + row * 132 + f4 * 4) = v;
    }
    __syncthreads();

    // ---- per-lane ldmatrix address patterns ----
    const int g4  = lane >> 2;            // fragment row group
    const int tig = lane & 3;             // thread-in-group
    const int m0  = wid * 16;
    const int t   = lane >> 3;            // ldmatrix tile index
    const int r8  = lane & 7;             // row within tile
    const uint32_t aoff = (uint32_t)(((m0 + (t & 1) * 8 + r8) * 136 + (t >> 1) * 8) * 2);
    const uint32_t boff = (uint32_t)((r8 * 136 + t * 8) * 2);
    const uint32_t aAg = sb + OFF_AG + aoff;
    const uint32_t aAh = sb + OFF_AH + aoff;
    const uint32_t bBx = sb + OFF_BX + boff;
    const uint32_t bBh = sb + OFF_BH + boff;

    float zreg[16][4], rreg[16][4], acc[16][4];

    // ================= gate 0 (z): acc = agg@Wx_z + h@Wh_z =================
    stage_B(smem, 0, tid);
    __syncthreads();
#pragma unroll
    for (int n = 0; n < 16; n++) { acc[n][0] = acc[n][1] = acc[n][2] = acc[n][3] = 0.f; }
    gemm_into(acc, aAg, bBx);
    gemm_into(acc, aAh, bBh);
#pragma unroll
    for (int n = 0; n < 16; n++) {
#pragma unroll
        for (int j = 0; j < 4; j++) {
            int col = n * 8 + tig * 2 + (j & 1);
            float v = acc[n][j] + bias_s[col] + bias_s[384 + col];
            zreg[n][j] = 1.f / (1.f + __expf(-v));
        }
    }
    __syncthreads();

    // ================= gate 1 (r): acc = agg@Wx_r + h@Wh_r =================
    stage_B(smem, 1, tid);
    __syncthreads();
#pragma unroll
    for (int n = 0; n < 16; n++) { acc[n][0] = acc[n][1] = acc[n][2] = acc[n][3] = 0.f; }
    gemm_into(acc, aAg, bBx);
    gemm_into(acc, aAh, bBh);
#pragma unroll
    for (int n = 0; n < 16; n++) {
#pragma unroll
        for (int j = 0; j < 4; j++) {
            int col = n * 8 + tig * 2 + (j & 1);
            float v = acc[n][j] + bias_s[128 + col] + bias_s[384 + 128 + col];
            rreg[n][j] = 1.f / (1.f + __expf(-v));
        }
    }
    __syncthreads();

    // ================= gate 2 (h) =================
    stage_B(smem, 2, tid);
    __syncthreads();

    // pass 1: rh = h @ Wh_h + bias;   r := r * rh  (in place, frees acc)
#pragma unroll
    for (int n = 0; n < 16; n++) { acc[n][0] = acc[n][1] = acc[n][2] = acc[n][3] = 0.f; }
    gemm_into(acc, aAh, bBh);
#pragma unroll
    for (int n = 0; n < 16; n++) {
#pragma unroll
        for (int j = 0; j < 4; j++) {
            int col = n * 8 + tig * 2 + (j & 1);
            rreg[n][j] *= (acc[n][j] + bias_s[384 + 256 + col]);
        }
    }

    // pass 2: xh = agg @ Wx_h + bias;  hh = tanh(xh + r*rh);  out = z*h + (1-z)*hh
#pragma unroll
    for (int n = 0; n < 16; n++) { acc[n][0] = acc[n][1] = acc[n][2] = acc[n][3] = 0.f; }
    gemm_into(acc, aAg, bBx);

    const int row_a = m0 + g4;
    const int row_b = m0 + g4 + 8;
#pragma unroll
    for (int n = 0; n < 16; n++) {
        int colb = n * 8 + tig * 2;
        float o[4];
#pragma unroll
        for (int j = 0; j < 4; j++) {
            int col = colb + (j & 1);
            int row = (j < 2) ? row_a : row_b;
            float xh = acc[n][j] + bias_s[256 + col];
            float hh = tanhf(xh + rreg[n][j]);
            float z  = zreg[n][j];
            float hf = hf_s[row * 132 + col];
            o[j] = z * hf + (1.f - z) * hh;
        }
        *reinterpret_cast<float2*>(out + (size_t)(row0 + row_a) * 128 + colb) = make_float2(o[0], o[1]);
        *reinterpret_cast<float2*>(out + (size_t)(row0 + row_b) * 128 + colb) = make_float2(o[2], o[3]);
    }
}

// ================================================================================
// Launch
// ================================================================================
extern "C" void kernel_launch(void* const* d_in, const int* in_sizes, int n_in,
                              void* d_out, int out_size) {
    const float* atom_state = (const float*)d_in[0];
    const float* messages   = (const float*)d_in[1];
    const int*   conn       = (const int*)d_in[2];
    const float* kern       = (const float*)d_in[3];
    const float* rker       = (const float*)d_in[4];
    const float* bias       = (const float*)d_in[5];
    float* out = (float*)d_out;

    static bool attr_set = false;
    if (!attr_set) {
        cudaFuncSetAttribute(gru_gemm_kernel, cudaFuncAttributeMaxDynamicSharedMemorySize, SMEM_TOTAL);
        attr_set = true;
    }

    prep_w_kernel<<<(2 * 384 * 128 + 255) / 256, 256>>>(kern, rker);
    zero_agg_kernel<<<4096, 256>>>();
    scatter_kernel<<<(NEDGE * 32) / 256, 256>>>(messages, conn);
    gru_gemm_kernel<<<ROWS_TOTAL / 128, 256, SMEM_TOTAL>>>(atom_state, bias, out);
}

// round 3
// speedup vs baseline: 2.2254x; 2.2254x over previous
#include <cuda_runtime.h>
#include <cuda_fp16.h>
#include <cstdint>

// Problem constants
#define B_  32
#define N_  4096
#define E_  8192
#define D_  128
#define ROWS_TOTAL (B_*N_)        // 131072
#define NEDGE (B_*E_)             // 262144

// ---------------- device-global scratch ------------------------------------------
__device__ float  g_agg[B_*N_*D_];         // 64MB aggregation buffer
__device__ __half g_wt[2*384*128];         // transposed fp16 weights: [mat][col(384)][k(128)]

// ---------------- smem layout (bytes) --------------------------------------------
// fp16 tiles: [128 rows][136 halves] (8-half pad -> 272B row stride, ldmatrix
// conflict-free).
#define OFF_BIAS  0                 // 768 floats
#define OFF_AG    3072              // agg fp16 tile   (34816 B)
#define OFF_AH    37888             // h   fp16 tile   (34816 B)
#define OFF_BX    72704             // Wx gate slice   (34816 B)
#define OFF_BH    107520            // Wh gate slice   (34816 B)
#define SMEM_TOTAL 142336

__device__ __forceinline__ uint32_t smem_u32(const void* p) {
    uint32_t a;
    asm("{ .reg .u64 t; cvta.to.shared.u64 t, %1; cvt.u32.u64 %0, t; }" : "=r"(a) : "l"(p));
    return a;
}

__device__ __forceinline__ void ldsm4(uint32_t d[4], uint32_t addr) {
    asm volatile("ldmatrix.sync.aligned.m8n8.x4.shared.b16 {%0,%1,%2,%3}, [%4];"
                 : "=r"(d[0]), "=r"(d[1]), "=r"(d[2]), "=r"(d[3]) : "r"(addr));
}

__device__ __forceinline__ void mma_16816(float c[4], const uint32_t a[4], uint32_t b0, uint32_t b1) {
    asm volatile(
        "mma.sync.aligned.m16n8k16.row.col.f32.f16.f16.f32 "
        "{%0,%1,%2,%3}, {%4,%5,%6,%7}, {%8,%9}, {%0,%1,%2,%3};"
        : "+f"(c[0]), "+f"(c[1]), "+f"(c[2]), "+f"(c[3])
        : "r"(a[0]), "r"(a[1]), "r"(a[2]), "r"(a[3]), "r"(b0), "r"(b1));
}

__device__ __forceinline__ float sigf(float x) { return 1.f / (1.f + __expf(-x)); }

// ================================================================================
// Kernel 1: transpose + fp16-convert weights:  g_wt[mat][col][k] = W[k*384+col]
// ================================================================================
__global__ void prep_w_kernel(const float* __restrict__ kern, const float* __restrict__ rker) {
    int i = blockIdx.x * blockDim.x + threadIdx.x;
    if (i >= 2 * 384 * 128) return;
    int mat = i / (384 * 128);
    int rem = i - mat * (384 * 128);
    int col = rem >> 7;
    int k   = rem & 127;
    const float* W = mat ? rker : kern;
    g_wt[i] = __float2half_rn(W[k * 384 + col]);
}

// ================================================================================
// Kernel 2: zero the aggregation scratch
// ================================================================================
__global__ void zero_agg_kernel() {
    const float4 z = make_float4(0.f, 0.f, 0.f, 0.f);
    int n4 = (B_ * N_ * D_) / 4;
    for (int i = blockIdx.x * blockDim.x + threadIdx.x; i < n4; i += gridDim.x * blockDim.x)
        reinterpret_cast<float4*>(g_agg)[i] = z;
}

// ================================================================================
// Kernel 3: scatter-add messages into g_agg.  One warp per edge, vector REDG.
// ================================================================================
__global__ void scatter_kernel(const float* __restrict__ msgs, const int* __restrict__ conn) {
    int gwarp = (blockIdx.x * blockDim.x + threadIdx.x) >> 5;
    int lane  = threadIdx.x & 31;
    if (gwarp >= NEDGE) return;
    int b = gwarp >> 13;                                  // / E_
    int tgt;
    if (lane == 0) tgt = conn[gwarp * 2 + 1];
    tgt = __shfl_sync(0xffffffffu, tgt, 0);
    float4 m = reinterpret_cast<const float4*>(msgs)[gwarp * 32 + lane];
    float* dst = g_agg + ((size_t)((b << 12) + tgt)) * 128 + lane * 4;
    asm volatile("red.global.add.v4.f32 [%0], {%1, %2, %3, %4};"
                 :: "l"(dst), "f"(m.x), "f"(m.y), "f"(m.z), "f"(m.w) : "memory");
}

// ================================================================================
// Kernel 4: fused dual-GEMM (mma.sync f16) + GRU epilogue.
// 1024 CTAs x 128 rows, 512 threads (16 warps, 4x4 grid, warp tile 32x32).
// ================================================================================

// Stage one gate's W slices (both mats) into smem, fp16 [128 n][136 k-halves].
__device__ __forceinline__ void stage_B(char* smem, int g, int tid) {
    for (int idx = tid; idx < 4096; idx += 512) {
        int mat = idx >> 11;
        int rem = idx & 2047;
        int n   = rem >> 4;
        int seg = rem & 15;     // 8 halves per seg
        uint4 v = reinterpret_cast<const uint4*>(
            g_wt + (size_t)(mat * 384 + g * 128 + n) * 128)[seg];
        *reinterpret_cast<uint4*>(smem + (mat ? OFF_BH : OFF_BX) + n * 272 + seg * 16) = v;
    }
}

// acc[mt][nt][j] += A(32x128) @ B(128x32)^T for this warp's 32x32 tile.
__device__ __forceinline__ void gemm_into(float (&acc)[2][4][4], uint32_t aBase, uint32_t bBase) {
#pragma unroll
    for (int kc = 0; kc < 4; kc++) {              // k32 chunks
        uint32_t A[2][2][4];
        uint32_t Bf[4][4];
#pragma unroll
        for (int mt = 0; mt < 2; mt++) {
            ldsm4(A[mt][0], aBase + mt * 4352 + kc * 64);        // k lo16
            ldsm4(A[mt][1], aBase + mt * 4352 + kc * 64 + 32);   // k hi16
        }
#pragma unroll
        for (int nt = 0; nt < 4; nt++)
            ldsm4(Bf[nt], bBase + nt * 2176 + kc * 64);          // n8 x k32
#pragma unroll
        for (int mt = 0; mt < 2; mt++)
#pragma unroll
            for (int nt = 0; nt < 4; nt++) {
                mma_16816(acc[mt][nt], A[mt][0], Bf[nt][0], Bf[nt][1]);
                mma_16816(acc[mt][nt], A[mt][1], Bf[nt][2], Bf[nt][3]);
            }
    }
}

__global__ void __launch_bounds__(512, 1)
gru_gemm_kernel(const float* __restrict__ atom_state,
                const float* __restrict__ bias,
                float* __restrict__ out)
{
    extern __shared__ char smem[];
    const uint32_t sb = smem_u32(smem);
    const int tid  = threadIdx.x;
    const int wid  = tid >> 5;
    const int lane = tid & 31;
    const int wr   = wid & 3;          // warp row group (32 rows)
    const int wc   = wid >> 2;         // warp col group (32 cols)
    const int row0 = blockIdx.x * 128;

    float* bias_s = reinterpret_cast<float*>(smem + OFF_BIAS);

    // ---- stage bias ----
    for (int i = tid; i < 768; i += 512) bias_s[i] = bias[i];

    // ---- stage A tiles: fp32 -> fp16 padded rows ----
    const float4* aggp = reinterpret_cast<const float4*>(g_agg + (size_t)row0 * 128);
    const float4* hp   = reinterpret_cast<const float4*>(atom_state + (size_t)row0 * 128);
    for (int idx = tid; idx < 2 * 128 * 32; idx += 512) {
        int src = idx >> 12;              // 0: agg, 1: h
        int rem = idx & 4095;
        int row = rem >> 5;
        int f4  = rem & 31;
        float4 v = src ? hp[rem] : aggp[rem];
        union { __half2 h2[2]; uint2 u; } cv;
        cv.h2[0] = __floats2half2_rn(v.x, v.y);
        cv.h2[1] = __floats2half2_rn(v.z, v.w);
        *reinterpret_cast<uint2*>(smem + (src ? OFF_AH : OFF_AG) + row * 272 + f4 * 8) = cv.u;
    }
    __syncthreads();

    // ---- per-lane ldmatrix address patterns ----
    const int g4  = lane >> 2;            // fragment row within 8
    const int tig = lane & 3;             // thread-in-group (col pair)
    const int t   = lane >> 3;            // ldmatrix tile index
    const int r8  = lane & 7;             // row within tile
    const uint32_t aoff = (uint32_t)(((wr * 32 + (t & 1) * 8 + r8) * 136 + (t >> 1) * 8) * 2);
    const uint32_t boff = (uint32_t)(((wc * 32 + r8) * 136 + t * 8) * 2);
    const uint32_t aAg = sb + OFF_AG + aoff;
    const uint32_t aAh = sb + OFF_AH + aoff;
    const uint32_t bBx = sb + OFF_BX + boff;
    const uint32_t bBh = sb + OFF_BH + boff;

    float acc[2][4][4];
    __half2 zpk[2][4][2];     // packed z
    __half2 rpk[2][4][2];     // packed r (later r*rh)

    // ================= gate 0 (z) =================
    stage_B(smem, 0, tid);
    __syncthreads();
#pragma unroll
    for (int mt = 0; mt < 2; mt++)
#pragma unroll
        for (int nt = 0; nt < 4; nt++)
            acc[mt][nt][0] = acc[mt][nt][1] = acc[mt][nt][2] = acc[mt][nt][3] = 0.f;
    gemm_into(acc, aAg, bBx);
    gemm_into(acc, aAh, bBh);
#pragma unroll
    for (int mt = 0; mt < 2; mt++)
#pragma unroll
        for (int nt = 0; nt < 4; nt++) {
            int colb = wc * 32 + nt * 8 + tig * 2;
            float b0 = bias_s[colb]     + bias_s[384 + colb];
            float b1 = bias_s[colb + 1] + bias_s[384 + colb + 1];
            zpk[mt][nt][0] = __floats2half2_rn(sigf(acc[mt][nt][0] + b0), sigf(acc[mt][nt][1] + b1));
            zpk[mt][nt][1] = __floats2half2_rn(sigf(acc[mt][nt][2] + b0), sigf(acc[mt][nt][3] + b1));
        }
    __syncthreads();

    // ================= gate 1 (r) =================
    stage_B(smem, 1, tid);
    __syncthreads();
#pragma unroll
    for (int mt = 0; mt < 2; mt++)
#pragma unroll
        for (int nt = 0; nt < 4; nt++)
            acc[mt][nt][0] = acc[mt][nt][1] = acc[mt][nt][2] = acc[mt][nt][3] = 0.f;
    gemm_into(acc, aAg, bBx);
    gemm_into(acc, aAh, bBh);
#pragma unroll
    for (int mt = 0; mt < 2; mt++)
#pragma unroll
        for (int nt = 0; nt < 4; nt++) {
            int colb = wc * 32 + nt * 8 + tig * 2;
            float b0 = bias_s[128 + colb]     + bias_s[384 + 128 + colb];
            float b1 = bias_s[128 + colb + 1] + bias_s[384 + 128 + colb + 1];
            rpk[mt][nt][0] = __floats2half2_rn(sigf(acc[mt][nt][0] + b0), sigf(acc[mt][nt][1] + b1));
            rpk[mt][nt][1] = __floats2half2_rn(sigf(acc[mt][nt][2] + b0), sigf(acc[mt][nt][3] + b1));
        }
    __syncthreads();

    // ================= gate 2 (h) =================
    stage_B(smem, 2, tid);
    __syncthreads();

    // pass 1: rh = h @ Wh_h + bias;   r := r * rh (packed, in place)
#pragma unroll
    for (int mt = 0; mt < 2; mt++)
#pragma unroll
        for (int nt = 0; nt < 4; nt++)
            acc[mt][nt][0] = acc[mt][nt][1] = acc[mt][nt][2] = acc[mt][nt][3] = 0.f;
    gemm_into(acc, aAh, bBh);
#pragma unroll
    for (int mt = 0; mt < 2; mt++)
#pragma unroll
        for (int nt = 0; nt < 4; nt++) {
            int colb = wc * 32 + nt * 8 + tig * 2;
            float b0 = bias_s[384 + 256 + colb];
            float b1 = bias_s[384 + 256 + colb + 1];
            float2 ra = __half22float2(rpk[mt][nt][0]);
            float2 rb = __half22float2(rpk[mt][nt][1]);
            rpk[mt][nt][0] = __floats2half2_rn(ra.x * (acc[mt][nt][0] + b0), ra.y * (acc[mt][nt][1] + b1));
            rpk[mt][nt][1] = __floats2half2_rn(rb.x * (acc[mt][nt][2] + b0), rb.y * (acc[mt][nt][3] + b1));
        }

    // pass 2: xh = agg @ Wx_h + bias; hh = tanh(xh + r*rh); out = z*h + (1-z)*hh
#pragma unroll
    for (int mt = 0; mt < 2; mt++)
#pragma unroll
        for (int nt = 0; nt < 4; nt++)
            acc[mt][nt][0] = acc[mt][nt][1] = acc[mt][nt][2] = acc[mt][nt][3] = 0.f;
    gemm_into(acc, aAg, bBx);

#pragma unroll
    for (int mt = 0; mt < 2; mt++) {
        const int row_a = row0 + wr * 32 + mt * 16 + g4;
        const int row_b = row_a + 8;
#pragma unroll
        for (int nt = 0; nt < 4; nt++) {
            int colb = wc * 32 + nt * 8 + tig * 2;
            float b0 = bias_s[256 + colb];
            float b1 = bias_s[256 + colb + 1];
            float2 tA = __half22float2(rpk[mt][nt][0]);
            float2 tB = __half22float2(rpk[mt][nt][1]);
            float2 zA = __half22float2(zpk[mt][nt][0]);
            float2 zB = __half22float2(zpk[mt][nt][1]);
            float2 hA = *reinterpret_cast<const float2*>(atom_state + (size_t)row_a * 128 + colb);
            float2 hB = *reinterpret_cast<const float2*>(atom_state + (size_t)row_b * 128 + colb);

            float hh0 = tanhf(acc[mt][nt][0] + b0 + tA.x);
            float hh1 = tanhf(acc[mt][nt][1] + b1 + tA.y);
            float hh2 = tanhf(acc[mt][nt][2] + b0 + tB.x);
            float hh3 = tanhf(acc[mt][nt][3] + b1 + tB.y);

            float2 oA = make_float2(zA.x * hA.x + (1.f - zA.x) * hh0,
                                    zA.y * hA.y + (1.f - zA.y) * hh1);
            float2 oB = make_float2(zB.x * hB.x + (1.f - zB.x) * hh2,
                                    zB.y * hB.y + (1.f - zB.y) * hh3);
            *reinterpret_cast<float2*>(out + (size_t)row_a * 128 + colb) = oA;
            *reinterpret_cast<float2*>(out + (size_t)row_b * 128 + colb) = oB;
        }
    }
}

// ================================================================================
// Launch
// ================================================================================
extern "C" void kernel_launch(void* const* d_in, const int* in_sizes, int n_in,
                              void* d_out, int out_size) {
    const float* atom_state = (const float*)d_in[0];
    const float* messages   = (const float*)d_in[1];
    const int*   conn       = (const int*)d_in[2];
    const float* kern       = (const float*)d_in[3];
    const float* rker       = (const float*)d_in[4];
    const float* bias       = (const float*)d_in[5];
    float* out = (float*)d_out;

    static bool attr_set = false;
    if (!attr_set) {
        cudaFuncSetAttribute(gru_gemm_kernel, cudaFuncAttributeMaxDynamicSharedMemorySize, SMEM_TOTAL);
        attr_set = true;
    }

    prep_w_kernel<<<(2 * 384 * 128 + 255) / 256, 256>>>(kern, rker);
    zero_agg_kernel<<<4096, 256>>>();
    scatter_kernel<<<(NEDGE * 32) / 256, 256>>>(messages, conn);
    gru_gemm_kernel<<<ROWS_TOTAL / 128, 512, SMEM_TOTAL>>>(atom_state, bias, out);
}

// round 4
// speedup vs baseline: 3.0496x; 1.3704x over previous
#include <cuda_runtime.h>
#include <cuda_fp16.h>
#include <cstdint>

// Problem constants
#define B_  32
#define N_  4096
#define E_  8192
#define D_  128
#define ROWS_TOTAL (B_*N_)        // 131072
#define NEDGE (B_*E_)             // 262144

// ---------------- device-global scratch ------------------------------------------
__device__ float  g_agg[B_*N_*D_];         // 64MB aggregation buffer
__device__ __half g_wt[2*384*128];         // transposed fp16 weights: [mat][col(384)][k(128)]

// ---------------- smem layout (bytes), per 64-row CTA ----------------------------
// fp16 tiles: [rows][136 halves] (8-half pad -> 272B row stride, ldmatrix clean).
#define OFF_BIAS  0                 // 768 floats (3072 B)
#define OFF_AG    3072              // agg fp16 tile 64x272  (17408 B)
#define OFF_AH    20480             // h   fp16 tile 64x272  (17408 B)
#define OFF_B0    37888             // B ring buf 0 128x272  (34816 B)
#define OFF_B1    72704             // B ring buf 1 128x272  (34816 B)
#define SMEM_TOTAL 107520           // < 113.5KB -> 2 CTAs/SM

__device__ __forceinline__ uint32_t smem_u32(const void* p) {
    uint32_t a;
    asm("{ .reg .u64 t; cvta.to.shared.u64 t, %1; cvt.u32.u64 %0, t; }" : "=r"(a) : "l"(p));
    return a;
}

__device__ __forceinline__ void ldsm4(uint32_t d[4], uint32_t addr) {
    asm volatile("ldmatrix.sync.aligned.m8n8.x4.shared.b16 {%0,%1,%2,%3}, [%4];"
                 : "=r"(d[0]), "=r"(d[1]), "=r"(d[2]), "=r"(d[3]) : "r"(addr));
}

__device__ __forceinline__ void mma_16816(float c[4], const uint32_t a[4], uint32_t b0, uint32_t b1) {
    asm volatile(
        "mma.sync.aligned.m16n8k16.row.col.f32.f16.f16.f32 "
        "{%0,%1,%2,%3}, {%4,%5,%6,%7}, {%8,%9}, {%0,%1,%2,%3};"
        : "+f"(c[0]), "+f"(c[1]), "+f"(c[2]), "+f"(c[3])
        : "r"(a[0]), "r"(a[1]), "r"(a[2]), "r"(a[3]), "r"(b0), "r"(b1));
}

__device__ __forceinline__ float sigf(float x) { return 1.f / (1.f + __expf(-x)); }

#define CP_ASYNC16(dst, src) \
    asm volatile("cp.async.cg.shared.global [%0], [%1], 16;" :: "r"(dst), "l"(src) : "memory")
#define CP_COMMIT() asm volatile("cp.async.commit_group;" ::: "memory")
#define CP_WAIT(n)  asm volatile("cp.async.wait_group %0;" :: "n"(n) : "memory")

// ================================================================================
// Kernel 1: transpose + fp16-convert weights:  g_wt[mat][col][k] = W[k*384+col]
// ================================================================================
__global__ void prep_w_kernel(const float* __restrict__ kern, const float* __restrict__ rker) {
    int i = blockIdx.x * blockDim.x + threadIdx.x;
    if (i >= 2 * 384 * 128) return;
    int mat = i / (384 * 128);
    int rem = i - mat * (384 * 128);
    int col = rem >> 7;
    int k   = rem & 127;
    const float* W = mat ? rker : kern;
    g_wt[i] = __float2half_rn(W[k * 384 + col]);
}

// ================================================================================
// Kernel 2: zero the aggregation scratch
// ================================================================================
__global__ void zero_agg_kernel() {
    const float4 z = make_float4(0.f, 0.f, 0.f, 0.f);
    int n4 = (B_ * N_ * D_) / 4;
    for (int i = blockIdx.x * blockDim.x + threadIdx.x; i < n4; i += gridDim.x * blockDim.x)
        reinterpret_cast<float4*>(g_agg)[i] = z;
}

// ================================================================================
// Kernel 3: scatter-add messages into g_agg.  One warp per edge, vector REDG.
// ================================================================================
__global__ void scatter_kernel(const float* __restrict__ msgs, const int* __restrict__ conn) {
    int gwarp = (blockIdx.x * blockDim.x + threadIdx.x) >> 5;
    int lane  = threadIdx.x & 31;
    if (gwarp >= NEDGE) return;
    int b = gwarp >> 13;                                  // / E_
    int tgt;
    if (lane == 0) tgt = conn[gwarp * 2 + 1];
    tgt = __shfl_sync(0xffffffffu, tgt, 0);
    float4 m = reinterpret_cast<const float4*>(msgs)[gwarp * 32 + lane];
    float* dst = g_agg + ((size_t)((b << 12) + tgt)) * 128 + lane * 4;
    asm volatile("red.global.add.v4.f32 [%0], {%1, %2, %3, %4};"
                 :: "l"(dst), "f"(m.x), "f"(m.y), "f"(m.z), "f"(m.w) : "memory");
}

// ================================================================================
// Kernel 4: fused dual-GEMM + GRU epilogue.
// 2048 CTAs x 64 rows, 256 threads (8 warps, 2x4 grid, warp tile 32x32).
// 6 B-phases (matrix x gate), cp.async double-buffered.
// ================================================================================

// phase -> (mat, gate):  p0:Wx_z p1:Wh_z p2:Wx_r p3:Wh_r p4:Wh_h p5:Wx_h
__device__ __forceinline__ void prefetch_B(uint32_t dstbase, int phase, int tid) {
    const int matv = (0x1A >> phase) & 1;         // 0,1,0,1,1,0
    const int gv   = phase >> 1;                  // 0,0,1,1,2,2
    const char* src = reinterpret_cast<const char*>(
        g_wt + (size_t)(matv * 384 + gv * 128) * 128);
#pragma unroll
    for (int k = 0; k < 8; k++) {
        int c = tid + k * 256;                    // 16B chunk index, 2048 total
        uint32_t dst = dstbase + (uint32_t)((c >> 4) * 272 + (c & 15) * 16);
        CP_ASYNC16(dst, src + (size_t)c * 16);
    }
    CP_COMMIT();
}

// acc += A(32x128) @ B(128x32)^T for this warp's 32x32 tile.
__device__ __forceinline__ void gemm_into(float (&acc)[2][4][4], uint32_t aBase, uint32_t bBase) {
#pragma unroll
    for (int kc = 0; kc < 4; kc++) {              // k32 chunks
        uint32_t A[2][2][4];
        uint32_t Bf[4][4];
#pragma unroll
        for (int mt = 0; mt < 2; mt++) {
            ldsm4(A[mt][0], aBase + mt * 4352 + kc * 64);        // k lo16
            ldsm4(A[mt][1], aBase + mt * 4352 + kc * 64 + 32);   // k hi16
        }
#pragma unroll
        for (int nt = 0; nt < 4; nt++)
            ldsm4(Bf[nt], bBase + nt * 2176 + kc * 64);          // n8 x k32
#pragma unroll
        for (int mt = 0; mt < 2; mt++)
#pragma unroll
            for (int nt = 0; nt < 4; nt++) {
                mma_16816(acc[mt][nt], A[mt][0], Bf[nt][0], Bf[nt][1]);
                mma_16816(acc[mt][nt], A[mt][1], Bf[nt][2], Bf[nt][3]);
            }
    }
}

#define ZERO_ACC() do { _Pragma("unroll") \
    for (int mt = 0; mt < 2; mt++) _Pragma("unroll") \
        for (int nt = 0; nt < 4; nt++) \
            acc[mt][nt][0] = acc[mt][nt][1] = acc[mt][nt][2] = acc[mt][nt][3] = 0.f; } while (0)

__global__ void __launch_bounds__(256, 2)
gru_gemm_kernel(const float* __restrict__ atom_state,
                const float* __restrict__ bias,
                float* __restrict__ out)
{
    extern __shared__ char smem[];
    const uint32_t sb = smem_u32(smem);
    const int tid  = threadIdx.x;
    const int wid  = tid >> 5;
    const int lane = tid & 31;
    const int wr   = wid & 1;          // warp row group (2 x 32 rows)
    const int wc   = wid >> 1;         // warp col group (4 x 32 cols)
    const int row0 = blockIdx.x * 64;

    float* bias_s = reinterpret_cast<float*>(smem + OFF_BIAS);

    // ---- start B prefetch for phases 0 and 1 immediately ----
    prefetch_B(sb + OFF_B0, 0, tid);
    prefetch_B(sb + OFF_B1, 1, tid);

    // ---- stage bias ----
    for (int i = tid; i < 768; i += 256) bias_s[i] = bias[i];

    // ---- stage A tiles: fp32 -> fp16 padded rows (batched loads for MLP) ----
    {
        const float4* aggp = reinterpret_cast<const float4*>(g_agg + (size_t)row0 * 128);
        const float4* hp   = reinterpret_cast<const float4*>(atom_state + (size_t)row0 * 128);
        float4 v[16];
#pragma unroll
        for (int k = 0; k < 16; k++) {
            int idx = tid + k * 256;              // 0..4095
            int src = idx >> 11;                  // 0: agg (2048 f4), 1: h
            int rem = idx & 2047;                 // row*32 + f4
            v[k] = src ? hp[rem] : aggp[rem];
        }
#pragma unroll
        for (int k = 0; k < 16; k++) {
            int idx = tid + k * 256;
            int src = idx >> 11;
            int rem = idx & 2047;
            int row = rem >> 5;
            int f4  = rem & 31;
            union { __half2 h2[2]; uint2 u; } cv;
            cv.h2[0] = __floats2half2_rn(v[k].x, v[k].y);
            cv.h2[1] = __floats2half2_rn(v[k].z, v[k].w);
            *reinterpret_cast<uint2*>(smem + (src ? OFF_AH : OFF_AG) + row * 272 + f4 * 8) = cv.u;
        }
    }

    // ---- per-lane ldmatrix address patterns ----
    const int g4  = lane >> 2;            // fragment row within 8
    const int tig = lane & 3;             // thread-in-group (col pair)
    const int t   = lane >> 3;            // ldmatrix tile index
    const int r8  = lane & 7;             // row within tile
    const uint32_t aoff = (uint32_t)(((wr * 32 + (t & 1) * 8 + r8) * 136 + (t >> 1) * 8) * 2);
    const uint32_t boff = (uint32_t)(((wc * 32 + r8) * 136 + t * 8) * 2);
    const uint32_t aAg = sb + OFF_AG + aoff;
    const uint32_t aAh = sb + OFF_AH + aoff;
    const uint32_t bB0 = sb + OFF_B0 + boff;
    const uint32_t bB1 = sb + OFF_B1 + boff;

    float acc[2][4][4];
    __half2 zpk[2][4][2];
    __half2 rpk[2][4][2];

    // ================= phase 0: acc = agg @ Wx_z =================
    CP_WAIT(1);
    __syncthreads();                      // B0 ready + A tiles ready
    ZERO_ACC();
    gemm_into(acc, aAg, bB0);
    __syncthreads();                      // done reading B0
    prefetch_B(sb + OFF_B0, 2, tid);

    // ================= phase 1: acc += h @ Wh_z  -> z =================
    CP_WAIT(1);
    __syncthreads();
    gemm_into(acc, aAh, bB1);
#pragma unroll
    for (int mt = 0; mt < 2; mt++)
#pragma unroll
        for (int nt = 0; nt < 4; nt++) {
            int colb = wc * 32 + nt * 8 + tig * 2;
            float b0 = bias_s[colb]     + bias_s[384 + colb];
            float b1 = bias_s[colb + 1] + bias_s[384 + colb + 1];
            zpk[mt][nt][0] = __floats2half2_rn(sigf(acc[mt][nt][0] + b0), sigf(acc[mt][nt][1] + b1));
            zpk[mt][nt][1] = __floats2half2_rn(sigf(acc[mt][nt][2] + b0), sigf(acc[mt][nt][3] + b1));
        }
    __syncthreads();
    prefetch_B(sb + OFF_B1, 3, tid);

    // ================= phase 2: acc = agg @ Wx_r =================
    CP_WAIT(1);
    __syncthreads();
    ZERO_ACC();
    gemm_into(acc, aAg, bB0);
    __syncthreads();
    prefetch_B(sb + OFF_B0, 4, tid);

    // ================= phase 3: acc += h @ Wh_r  -> r =================
    CP_WAIT(1);
    __syncthreads();
    gemm_into(acc, aAh, bB1);
#pragma unroll
    for (int mt = 0; mt < 2; mt++)
#pragma unroll
        for (int nt = 0; nt < 4; nt++) {
            int colb = wc * 32 + nt * 8 + tig * 2;
            float b0 = bias_s[128 + colb]     + bias_s[384 + 128 + colb];
            float b1 = bias_s[128 + colb + 1] + bias_s[384 + 128 + colb + 1];
            rpk[mt][nt][0] = __floats2half2_rn(sigf(acc[mt][nt][0] + b0), sigf(acc[mt][nt][1] + b1));
            rpk[mt][nt][1] = __floats2half2_rn(sigf(acc[mt][nt][2] + b0), sigf(acc[mt][nt][3] + b1));
        }
    __syncthreads();
    prefetch_B(sb + OFF_B1, 5, tid);

    // ================= phase 4: acc = h @ Wh_h ; r := r*(acc+b) =================
    CP_WAIT(1);
    __syncthreads();
    ZERO_ACC();
    gemm_into(acc, aAh, bB0);
#pragma unroll
    for (int mt = 0; mt < 2; mt++)
#pragma unroll
        for (int nt = 0; nt < 4; nt++) {
            int colb = wc * 32 + nt * 8 + tig * 2;
            float b0 = bias_s[384 + 256 + colb];
            float b1 = bias_s[384 + 256 + colb + 1];
            float2 ra = __half22float2(rpk[mt][nt][0]);
            float2 rb = __half22float2(rpk[mt][nt][1]);
            rpk[mt][nt][0] = __floats2half2_rn(ra.x * (acc[mt][nt][0] + b0), ra.y * (acc[mt][nt][1] + b1));
            rpk[mt][nt][1] = __floats2half2_rn(rb.x * (acc[mt][nt][2] + b0), rb.y * (acc[mt][nt][3] + b1));
        }
    // no sync needed: phase 5's buffer (B1) was prefetched before phase 4

    // ================= phase 5: acc = agg @ Wx_h ; final epilogue =================
    CP_WAIT(0);
    __syncthreads();
    ZERO_ACC();
    gemm_into(acc, aAg, bB1);

#pragma unroll
    for (int mt = 0; mt < 2; mt++) {
        const int lrow_a = wr * 32 + mt * 16 + g4;
        const int lrow_b = lrow_a + 8;
#pragma unroll
        for (int nt = 0; nt < 4; nt++) {
            int colb = wc * 32 + nt * 8 + tig * 2;
            float b0 = bias_s[256 + colb];
            float b1 = bias_s[256 + colb + 1];
            float2 tA = __half22float2(rpk[mt][nt][0]);
            float2 tB = __half22float2(rpk[mt][nt][1]);
            float2 zA = __half22float2(zpk[mt][nt][0]);
            float2 zB = __half22float2(zpk[mt][nt][1]);
            // h (fp16) from the staged A tile in smem
            float2 hA = __half22float2(*reinterpret_cast<const __half2*>(
                smem + OFF_AH + lrow_a * 272 + colb * 2));
            float2 hB = __half22float2(*reinterpret_cast<const __half2*>(
                smem + OFF_AH + lrow_b * 272 + colb * 2));

            float hh0 = tanhf(acc[mt][nt][0] + b0 + tA.x);
            float hh1 = tanhf(acc[mt][nt][1] + b1 + tA.y);
            float hh2 = tanhf(acc[mt][nt][2] + b0 + tB.x);
            float hh3 = tanhf(acc[mt][nt][3] + b1 + tB.y);

            float2 oA = make_float2(zA.x * hA.x + (1.f - zA.x) * hh0,
                                    zA.y * hA.y + (1.f - zA.y) * hh1);
            float2 oB = make_float2(zB.x * hB.x + (1.f - zB.x) * hh2,
                                    zB.y * hB.y + (1.f - zB.y) * hh3);
            *reinterpret_cast<float2*>(out + (size_t)(row0 + lrow_a) * 128 + colb) = oA;
            *reinterpret_cast<float2*>(out + (size_t)(row0 + lrow_b) * 128 + colb) = oB;
        }
    }
}

// ================================================================================
// Launch
// ================================================================================
extern "C" void kernel_launch(void* const* d_in, const int* in_sizes, int n_in,
                              void* d_out, int out_size) {
    const float* atom_state = (const float*)d_in[0];
    const float* messages   = (const float*)d_in[1];
    const int*   conn       = (const int*)d_in[2];
    const float* kern       = (const float*)d_in[3];
    const float* rker       = (const float*)d_in[4];
    const float* bias       = (const float*)d_in[5];
    float* out = (float*)d_out;

    static bool attr_set = false;
    if (!attr_set) {
        cudaFuncSetAttribute(gru_gemm_kernel, cudaFuncAttributeMaxDynamicSharedMemorySize, SMEM_TOTAL);
        attr_set = true;
    }

    prep_w_kernel<<<(2 * 384 * 128 + 255) / 256, 256>>>(kern, rker);
    zero_agg_kernel<<<4096, 256>>>();
    scatter_kernel<<<(NEDGE * 32) / 256, 256>>>(messages, conn);
    gru_gemm_kernel<<<ROWS_TOTAL / 64, 256, SMEM_TOTAL>>>(atom_state, bias, out);
}

// round 5
// speedup vs baseline: 3.3364x; 1.0941x over previous
#include <cuda_runtime.h>
#include <cuda_fp16.h>
#include <cstdint>

// Problem constants
#define B_  32
#define N_  4096
#define E_  8192
#define D_  128
#define ROWS_TOTAL (B_*N_)        // 131072
#define NEDGE (B_*E_)             // 262144

// ---------------- device-global scratch ------------------------------------------
__device__ __half g_agg[B_*N_*D_];         // 32MB fp16 aggregation buffer
__device__ __half g_wt[2*384*128];         // transposed fp16 weights: [mat][col(384)][k(128)]

// ---------------- smem layout (bytes), per 64-row CTA ----------------------------
// fp16 tiles: [rows][136 halves] (8-half pad -> 272B row stride, ldmatrix clean).
#define OFF_BIAS  0                 // 768 floats (3072 B)
#define OFF_AG    3072              // agg fp16 tile 64x272  (17408 B)
#define OFF_AH    20480             // h   fp16 tile 64x272  (17408 B)
#define OFF_B0    37888             // B ring buf 0 128x272  (34816 B)
#define OFF_B1    72704             // B ring buf 1 128x272  (34816 B)
#define SMEM_TOTAL 107520           // < 113.5KB -> 2 CTAs/SM

__device__ __forceinline__ uint32_t smem_u32(const void* p) {
    uint32_t a;
    asm("{ .reg .u64 t; cvta.to.shared.u64 t, %1; cvt.u32.u64 %0, t; }" : "=r"(a) : "l"(p));
    return a;
}

__device__ __forceinline__ void ldsm4(uint32_t d[4], uint32_t addr) {
    asm volatile("ldmatrix.sync.aligned.m8n8.x4.shared.b16 {%0,%1,%2,%3}, [%4];"
                 : "=r"(d[0]), "=r"(d[1]), "=r"(d[2]), "=r"(d[3]) : "r"(addr));
}

__device__ __forceinline__ void mma_16816(float c[4], const uint32_t a[4], uint32_t b0, uint32_t b1) {
    asm volatile(
        "mma.sync.aligned.m16n8k16.row.col.f32.f16.f16.f32 "
        "{%0,%1,%2,%3}, {%4,%5,%6,%7}, {%8,%9}, {%0,%1,%2,%3};"
        : "+f"(c[0]), "+f"(c[1]), "+f"(c[2]), "+f"(c[3])
        : "r"(a[0]), "r"(a[1]), "r"(a[2]), "r"(a[3]), "r"(b0), "r"(b1));
}

__device__ __forceinline__ float sigf(float x) { return 1.f / (1.f + __expf(-x)); }

#define CP_ASYNC16(dst, src) \
    asm volatile("cp.async.cg.shared.global [%0], [%1], 16;" :: "r"(dst), "l"(src) : "memory")
#define CP_COMMIT() asm volatile("cp.async.commit_group;" ::: "memory")
#define CP_WAIT(n)  asm volatile("cp.async.wait_group %0;" :: "n"(n) : "memory")

// ================================================================================
// Kernel 1: transpose + fp16-convert weights:  g_wt[mat][col][k] = W[k*384+col]
// ================================================================================
__global__ void prep_w_kernel(const float* __restrict__ kern, const float* __restrict__ rker) {
    int i = blockIdx.x * blockDim.x + threadIdx.x;
    if (i >= 2 * 384 * 128) return;
    int mat = i / (384 * 128);
    int rem = i - mat * (384 * 128);
    int col = rem >> 7;
    int k   = rem & 127;
    const float* W = mat ? rker : kern;
    g_wt[i] = __float2half_rn(W[k * 384 + col]);
}

// ================================================================================
// Kernel 2: zero the fp16 aggregation scratch (32MB)
// ================================================================================
__global__ void zero_agg_kernel() {
    const uint4 z = make_uint4(0u, 0u, 0u, 0u);
    int n16 = (B_ * N_ * D_ * 2) / 16;   // 16B chunks
    for (int i = blockIdx.x * blockDim.x + threadIdx.x; i < n16; i += gridDim.x * blockDim.x)
        reinterpret_cast<uint4*>(g_agg)[i] = z;
}

// ================================================================================
// Kernel 3: scatter-add messages into fp16 g_agg.  Warp per edge, v2.f16x2 REDG.
// ================================================================================
__global__ void scatter_kernel(const float* __restrict__ msgs, const int* __restrict__ conn) {
    int gwarp = (blockIdx.x * blockDim.x + threadIdx.x) >> 5;
    int lane  = threadIdx.x & 31;
    if (gwarp >= NEDGE) return;
    int b = gwarp >> 13;                                  // / E_
    int tgt;
    if (lane == 0) tgt = conn[gwarp * 2 + 1];
    tgt = __shfl_sync(0xffffffffu, tgt, 0);
    float4 m = reinterpret_cast<const float4*>(msgs)[gwarp * 32 + lane];
    union { __half2 h; uint32_t u; } p0, p1;
    p0.h = __floats2half2_rn(m.x, m.y);
    p1.h = __floats2half2_rn(m.z, m.w);
    __half* dst = g_agg + ((size_t)((b << 12) + tgt)) * 128 + lane * 4;
    asm volatile("red.global.add.noftz.v2.f16x2 [%0], {%1, %2};"
                 :: "l"(dst), "r"(p0.u), "r"(p1.u) : "memory");
}

// ================================================================================
// Kernel 4: fused dual-GEMM + GRU epilogue.
// 2048 CTAs x 64 rows, 256 threads (8 warps, 2x4 grid, warp tile 32x32).
// 6 B-phases (matrix x gate), cp.async double-buffered; agg A-tile via cp.async.
// ================================================================================

// phase -> (mat, gate):  p0:Wx_z p1:Wh_z p2:Wx_r p3:Wh_r p4:Wh_h p5:Wx_h
__device__ __forceinline__ void prefetch_B(uint32_t dstbase, int phase, int tid) {
    const int matv = (0x1A >> phase) & 1;         // 0,1,0,1,1,0
    const int gv   = phase >> 1;                  // 0,0,1,1,2,2
    const char* src = reinterpret_cast<const char*>(
        g_wt + (size_t)(matv * 384 + gv * 128) * 128);
#pragma unroll
    for (int k = 0; k < 8; k++) {
        int c = tid + k * 256;                    // 16B chunk index, 2048 total
        uint32_t dst = dstbase + (uint32_t)((c >> 4) * 272 + (c & 15) * 16);
        CP_ASYNC16(dst, src + (size_t)c * 16);
    }
    CP_COMMIT();
}

// agg tile (fp16 in gmem) straight into padded smem layout: 64 rows x 256B.
__device__ __forceinline__ void prefetch_A_agg(uint32_t dstbase, const __half* src, int tid) {
    const char* s = reinterpret_cast<const char*>(src);
#pragma unroll
    for (int k = 0; k < 4; k++) {
        int c = tid + k * 256;                    // 16B chunk index, 1024 total
        uint32_t dst = dstbase + (uint32_t)((c >> 4) * 272 + (c & 15) * 16);
        CP_ASYNC16(dst, s + (size_t)c * 16);
    }
    CP_COMMIT();
}

// acc += A(32x128) @ B(128x32)^T for this warp's 32x32 tile.
__device__ __forceinline__ void gemm_into(float (&acc)[2][4][4], uint32_t aBase, uint32_t bBase) {
#pragma unroll
    for (int kc = 0; kc < 4; kc++) {              // k32 chunks
        uint32_t A[2][2][4];
        uint32_t Bf[4][4];
#pragma unroll
        for (int mt = 0; mt < 2; mt++) {
            ldsm4(A[mt][0], aBase + mt * 4352 + kc * 64);        // k lo16
            ldsm4(A[mt][1], aBase + mt * 4352 + kc * 64 + 32);   // k hi16
        }
#pragma unroll
        for (int nt = 0; nt < 4; nt++)
            ldsm4(Bf[nt], bBase + nt * 2176 + kc * 64);          // n8 x k32
#pragma unroll
        for (int mt = 0; mt < 2; mt++)
#pragma unroll
            for (int nt = 0; nt < 4; nt++) {
                mma_16816(acc[mt][nt], A[mt][0], Bf[nt][0], Bf[nt][1]);
                mma_16816(acc[mt][nt], A[mt][1], Bf[nt][2], Bf[nt][3]);
            }
    }
}

#define ZERO_ACC() do { _Pragma("unroll") \
    for (int mt = 0; mt < 2; mt++) _Pragma("unroll") \
        for (int nt = 0; nt < 4; nt++) \
            acc[mt][nt][0] = acc[mt][nt][1] = acc[mt][nt][2] = acc[mt][nt][3] = 0.f; } while (0)

__global__ void __launch_bounds__(256, 2)
gru_gemm_kernel(const float* __restrict__ atom_state,
                const float* __restrict__ bias,
                float* __restrict__ out)
{
    extern __shared__ char smem[];
    const uint32_t sb = smem_u32(smem);
    const int tid  = threadIdx.x;
    const int wid  = tid >> 5;
    const int lane = tid & 31;
    const int wr   = wid & 1;          // warp row group (2 x 32 rows)
    const int wc   = wid >> 1;         // warp col group (4 x 32 cols)
    const int row0 = blockIdx.x * 64;

    float* bias_s = reinterpret_cast<float*>(smem + OFF_BIAS);

    // ---- async prefetches: B(p0) [g0], agg A-tile [g1], B(p1) [g2] ----
    prefetch_B(sb + OFF_B0, 0, tid);
    prefetch_A_agg(sb + OFF_AG, g_agg + (size_t)row0 * 128, tid);
    prefetch_B(sb + OFF_B1, 1, tid);

    // ---- stage bias ----
    for (int i = tid; i < 768; i += 256) bias_s[i] = bias[i];

    // ---- stage h A-tile: fp32 -> fp16 padded rows (batched loads for MLP) ----
    {
        const float4* hp = reinterpret_cast<const float4*>(atom_state + (size_t)row0 * 128);
        float4 v[8];
#pragma unroll
        for (int k = 0; k < 8; k++)
            v[k] = hp[tid + k * 256];             // 2048 f4
#pragma unroll
        for (int k = 0; k < 8; k++) {
            int idx = tid + k * 256;
            int row = idx >> 5;
            int f4  = idx & 31;
            union { __half2 h2[2]; uint2 u; } cv;
            cv.h2[0] = __floats2half2_rn(v[k].x, v[k].y);
            cv.h2[1] = __floats2half2_rn(v[k].z, v[k].w);
            *reinterpret_cast<uint2*>(smem + OFF_AH + row * 272 + f4 * 8) = cv.u;
        }
    }

    // ---- per-lane ldmatrix address patterns ----
    const int g4  = lane >> 2;            // fragment row within 8
    const int tig = lane & 3;             // thread-in-group (col pair)
    const int t   = lane >> 3;            // ldmatrix tile index
    const int r8  = lane & 7;             // row within tile
    const uint32_t aoff = (uint32_t)(((wr * 32 + (t & 1) * 8 + r8) * 136 + (t >> 1) * 8) * 2);
    const uint32_t boff = (uint32_t)(((wc * 32 + r8) * 136 + t * 8) * 2);
    const uint32_t aAg = sb + OFF_AG + aoff;
    const uint32_t aAh = sb + OFF_AH + aoff;
    const uint32_t bB0 = sb + OFF_B0 + boff;
    const uint32_t bB1 = sb + OFF_B1 + boff;

    float acc[2][4][4];
    __half2 zpk[2][4][2];
    __half2 rpk[2][4][2];

    // ================= phase 0: acc = agg @ Wx_z =================
    CP_WAIT(1);                           // B0 + agg done (B1 still in flight)
    __syncthreads();
    ZERO_ACC();
    gemm_into(acc, aAg, bB0);
    __syncthreads();                      // done reading B0
    prefetch_B(sb + OFF_B0, 2, tid);

    // ================= phase 1: acc += h @ Wh_z  -> z =================
    CP_WAIT(1);
    __syncthreads();
    gemm_into(acc, aAh, bB1);
#pragma unroll
    for (int mt = 0; mt < 2; mt++)
#pragma unroll
        for (int nt = 0; nt < 4; nt++) {
            int colb = wc * 32 + nt * 8 + tig * 2;
            float b0 = bias_s[colb]     + bias_s[384 + colb];
            float b1 = bias_s[colb + 1] + bias_s[384 + colb + 1];
            zpk[mt][nt][0] = __floats2half2_rn(sigf(acc[mt][nt][0] + b0), sigf(acc[mt][nt][1] + b1));
            zpk[mt][nt][1] = __floats2half2_rn(sigf(acc[mt][nt][2] + b0), sigf(acc[mt][nt][3] + b1));
        }
    __syncthreads();
    prefetch_B(sb + OFF_B1, 3, tid);

    // ================= phase 2: acc = agg @ Wx_r =================
    CP_WAIT(1);
    __syncthreads();
    ZERO_ACC();
    gemm_into(acc, aAg, bB0);
    __syncthreads();
    prefetch_B(sb + OFF_B0, 4, tid);

    // ================= phase 3: acc += h @ Wh_r  -> r =================
    CP_WAIT(1);
    __syncthreads();
    gemm_into(acc, aAh, bB1);
#pragma unroll
    for (int mt = 0; mt < 2; mt++)
#pragma unroll
        for (int nt = 0; nt < 4; nt++) {
            int colb = wc * 32 + nt * 8 + tig * 2;
            float b0 = bias_s[128 + colb]     + bias_s[384 + 128 + colb];
            float b1 = bias_s[128 + colb + 1] + bias_s[384 + 128 + colb + 1];
            rpk[mt][nt][0] = __floats2half2_rn(sigf(acc[mt][nt][0] + b0), sigf(acc[mt][nt][1] + b1));
            rpk[mt][nt][1] = __floats2half2_rn(sigf(acc[mt][nt][2] + b0), sigf(acc[mt][nt][3] + b1));
        }
    __syncthreads();
    prefetch_B(sb + OFF_B1, 5, tid);

    // ================= phase 4: acc = h @ Wh_h ; r := r*(acc+b) =================
    CP_WAIT(1);
    __syncthreads();
    ZERO_ACC();
    gemm_into(acc, aAh, bB0);
#pragma unroll
    for (int mt = 0; mt < 2; mt++)
#pragma unroll
        for (int nt = 0; nt < 4; nt++) {
            int colb = wc * 32 + nt * 8 + tig * 2;
            float b0 = bias_s[384 + 256 + colb];
            float b1 = bias_s[384 + 256 + colb + 1];
            float2 ra = __half22float2(rpk[mt][nt][0]);
            float2 rb = __half22float2(rpk[mt][nt][1]);
            rpk[mt][nt][0] = __floats2half2_rn(ra.x * (acc[mt][nt][0] + b0), ra.y * (acc[mt][nt][1] + b1));
            rpk[mt][nt][1] = __floats2half2_rn(rb.x * (acc[mt][nt][2] + b0), rb.y * (acc[mt][nt][3] + b1));
        }
    // no sync needed: phase 5's buffer (B1) was prefetched before phase 4

    // ================= phase 5: acc = agg @ Wx_h ; final epilogue =================
    CP_WAIT(0);
    __syncthreads();
    ZERO_ACC();
    gemm_into(acc, aAg, bB1);

#pragma unroll
    for (int mt = 0; mt < 2; mt++) {
        const int lrow_a = wr * 32 + mt * 16 + g4;
        const int lrow_b = lrow_a + 8;
#pragma unroll
        for (int nt = 0; nt < 4; nt++) {
            int colb = wc * 32 + nt * 8 + tig * 2;
            float b0 = bias_s[256 + colb];
            float b1 = bias_s[256 + colb + 1];
            float2 tA = __half22float2(rpk[mt][nt][0]);
            float2 tB = __half22float2(rpk[mt][nt][1]);
            float2 zA = __half22float2(zpk[mt][nt][0]);
            float2 zB = __half22float2(zpk[mt][nt][1]);
            float2 hA = __half22float2(*reinterpret_cast<const __half2*>(
                smem + OFF_AH + lrow_a * 272 + colb * 2));
            float2 hB = __half22float2(*reinterpret_cast<const __half2*>(
                smem + OFF_AH + lrow_b * 272 + colb * 2));

            float hh0 = tanhf(acc[mt][nt][0] + b0 + tA.x);
            float hh1 = tanhf(acc[mt][nt][1] + b1 + tA.y);
            float hh2 = tanhf(acc[mt][nt][2] + b0 + tB.x);
            float hh3 = tanhf(acc[mt][nt][3] + b1 + tB.y);

            float2 oA = make_float2(zA.x * hA.x + (1.f - zA.x) * hh0,
                                    zA.y * hA.y + (1.f - zA.y) * hh1);
            float2 oB = make_float2(zB.x * hB.x + (1.f - zB.x) * hh2,
                                    zB.y * hB.y + (1.f - zB.y) * hh3);
            *reinterpret_cast<float2*>(out + (size_t)(row0 + lrow_a) * 128 + colb) = oA;
            *reinterpret_cast<float2*>(out + (size_t)(row0 + lrow_b) * 128 + colb) = oB;
        }
    }
}

// ================================================================================
// Launch
// ================================================================================
extern "C" void kernel_launch(void* const* d_in, const int* in_sizes, int n_in,
                              void* d_out, int out_size) {
    const float* atom_state = (const float*)d_in[0];
    const float* messages   = (const float*)d_in[1];
    const int*   conn       = (const int*)d_in[2];
    const float* kern       = (const float*)d_in[3];
    const float* rker       = (const float*)d_in[4];
    const float* bias       = (const float*)d_in[5];
    float* out = (float*)d_out;

    static bool attr_set = false;
    if (!attr_set) {
        cudaFuncSetAttribute(gru_gemm_kernel, cudaFuncAttributeMaxDynamicSharedMemorySize, SMEM_TOTAL);
        attr_set = true;
    }

    prep_w_kernel<<<(2 * 384 * 128 + 255) / 256, 256>>>(kern, rker);
    zero_agg_kernel<<<2048, 256>>>();
    scatter_kernel<<<(NEDGE * 32) / 256, 256>>>(messages, conn);
    gru_gemm_kernel<<<ROWS_TOTAL / 64, 256, SMEM_TOTAL>>>(atom_state, bias, out);
}

// round 6
// speedup vs baseline: 4.0961x; 1.2277x over previous
#include <cuda_runtime.h>
#include <cuda_fp16.h>
#include <cstdint>

// Problem constants
#define B_  32
#define N_  4096
#define E_  8192
#define D_  128
#define ROWS_TOTAL (B_*N_)        // 131072
#define NEDGE (B_*E_)             // 262144

// ---------------- device-global scratch ------------------------------------------
__device__ __half g_agg[B_*N_*D_];         // 32MB fp16 aggregation buffer
__device__ __half g_wt[2*384*128];         // transposed fp16 weights: [mat][col(384)][k(128)]

// ---------------- smem layout (bytes), per 64-row CTA ----------------------------
// fp16 tiles: [rows][136 halves] (8-half pad -> 272B row stride, ldmatrix clean).
#define OFF_BIAS  0                 // 768 floats (3072 B)
#define OFF_AG    3072              // agg fp16 tile 64x272  (17408 B)
#define OFF_AH    20480             // h   fp16 tile 64x272  (17408 B)
#define OFF_B0    37888             // B ring buf 0 128x272  (34816 B)
#define OFF_B1    72704             // B ring buf 1 128x272  (34816 B)
#define SMEM_TOTAL 107520           // < 113.5KB -> 2 CTAs/SM

__device__ __forceinline__ uint32_t smem_u32(const void* p) {
    uint32_t a;
    asm("{ .reg .u64 t; cvta.to.shared.u64 t, %1; cvt.u32.u64 %0, t; }" : "=r"(a) : "l"(p));
    return a;
}

__device__ __forceinline__ void ldsm4(uint32_t d[4], uint32_t addr) {
    asm volatile("ldmatrix.sync.aligned.m8n8.x4.shared.b16 {%0,%1,%2,%3}, [%4];"
                 : "=r"(d[0]), "=r"(d[1]), "=r"(d[2]), "=r"(d[3]) : "r"(addr));
}

__device__ __forceinline__ void mma_16816(float c[4], const uint32_t a[4], uint32_t b0, uint32_t b1) {
    asm volatile(
        "mma.sync.aligned.m16n8k16.row.col.f32.f16.f16.f32 "
        "{%0,%1,%2,%3}, {%4,%5,%6,%7}, {%8,%9}, {%0,%1,%2,%3};"
        : "+f"(c[0]), "+f"(c[1]), "+f"(c[2]), "+f"(c[3])
        : "r"(a[0]), "r"(a[1]), "r"(a[2]), "r"(a[3]), "r"(b0), "r"(b1));
}

__device__ __forceinline__ float tanh_ap(float x) {
    float y;
    asm("tanh.approx.f32 %0, %1;" : "=f"(y) : "f"(x));
    return y;
}
// sigmoid via MUFU.TANH: sigma(x) = 0.5*tanh(x/2) + 0.5
__device__ __forceinline__ float sigf(float x) { return fmaf(0.5f, tanh_ap(0.5f * x), 0.5f); }

#define CP_ASYNC16(dst, src) \
    asm volatile("cp.async.cg.shared.global [%0], [%1], 16;" :: "r"(dst), "l"(src) : "memory")
#define CP_COMMIT() asm volatile("cp.async.commit_group;" ::: "memory")
#define CP_WAIT(n)  asm volatile("cp.async.wait_group %0;" :: "n"(n) : "memory")

// ================================================================================
// Kernel 1: transpose + fp16-convert weights:  g_wt[mat][col][k] = W[k*384+col]
// ================================================================================
__global__ void prep_w_kernel(const float* __restrict__ kern, const float* __restrict__ rker) {
    int i = blockIdx.x * blockDim.x + threadIdx.x;
    if (i >= 2 * 384 * 128) return;
    int mat = i / (384 * 128);
    int rem = i - mat * (384 * 128);
    int col = rem >> 7;
    int k   = rem & 127;
    const float* W = mat ? rker : kern;
    g_wt[i] = __float2half_rn(W[k * 384 + col]);
}

// ================================================================================
// Kernel 2: zero the fp16 aggregation scratch (32MB)
// ================================================================================
__global__ void zero_agg_kernel() {
    const uint4 z = make_uint4(0u, 0u, 0u, 0u);
    int n16 = (B_ * N_ * D_ * 2) / 16;   // 16B chunks
    for (int i = blockIdx.x * blockDim.x + threadIdx.x; i < n16; i += gridDim.x * blockDim.x)
        reinterpret_cast<uint4*>(g_agg)[i] = z;
}

// ================================================================================
// Kernel 3: scatter-add into fp16 g_agg.  2 edges/warp, 16 lanes/edge,
// v4.f16x2 (16B) vector reduction.
// ================================================================================
__global__ void scatter_kernel(const float* __restrict__ msgs, const int* __restrict__ conn) {
    int gwarp = (blockIdx.x * blockDim.x + threadIdx.x) >> 5;
    int lane  = threadIdx.x & 31;
    int edge  = gwarp * 2 + (lane >> 4);              // 2 edges per warp
    if (edge >= NEDGE) return;
    int sub   = lane & 15;                            // lane within edge
    int b     = edge >> 13;                           // / E_

    int tgt;
    if (sub == 0) tgt = conn[edge * 2 + 1];
    tgt = __shfl_sync(0xffffffffu, tgt, lane & 16);   // broadcast within half-warp

    // floats 8*sub .. 8*sub+7 of this edge's message
    const float4* mp = reinterpret_cast<const float4*>(msgs) + (size_t)edge * 32 + sub * 2;
    float4 m0 = mp[0];
    float4 m1 = mp[1];
    union { __half2 h; uint32_t u; } p0, p1, p2, p3;
    p0.h = __floats2half2_rn(m0.x, m0.y);
    p1.h = __floats2half2_rn(m0.z, m0.w);
    p2.h = __floats2half2_rn(m1.x, m1.y);
    p3.h = __floats2half2_rn(m1.z, m1.w);
    __half* dst = g_agg + ((size_t)((b << 12) + tgt)) * 128 + sub * 8;
    asm volatile("red.global.add.noftz.v4.f16x2 [%0], {%1, %2, %3, %4};"
                 :: "l"(dst), "r"(p0.u), "r"(p1.u), "r"(p2.u), "r"(p3.u) : "memory");
}

// ================================================================================
// Kernel 4: fused dual-GEMM + GRU epilogue.
// 2048 CTAs x 64 rows, 256 threads (8 warps, 2x4 grid, warp tile 32x32).
// 6 B-phases, cp.async double-buffered; agg A-tile via cp.async; h LDGs hoisted.
// ================================================================================

// phase -> (mat, gate):  p0:Wx_z p1:Wh_z p2:Wx_r p3:Wh_r p4:Wh_h p5:Wx_h
__device__ __forceinline__ void prefetch_B(uint32_t dstbase, int phase, int tid) {
    const int matv = (0x1A >> phase) & 1;         // 0,1,0,1,1,0
    const int gv   = phase >> 1;                  // 0,0,1,1,2,2
    const char* src = reinterpret_cast<const char*>(
        g_wt + (size_t)(matv * 384 + gv * 128) * 128);
#pragma unroll
    for (int k = 0; k < 8; k++) {
        int c = tid + k * 256;                    // 16B chunk index, 2048 total
        uint32_t dst = dstbase + (uint32_t)((c >> 4) * 272 + (c & 15) * 16);
        CP_ASYNC16(dst, src + (size_t)c * 16);
    }
    CP_COMMIT();
}

// agg tile (fp16 in gmem) straight into padded smem layout: 64 rows x 256B.
__device__ __forceinline__ void prefetch_A_agg(uint32_t dstbase, const __half* src, int tid) {
    const char* s = reinterpret_cast<const char*>(src);
#pragma unroll
    for (int k = 0; k < 4; k++) {
        int c = tid + k * 256;                    // 16B chunk index, 1024 total
        uint32_t dst = dstbase + (uint32_t)((c >> 4) * 272 + (c & 15) * 16);
        CP_ASYNC16(dst, s + (size_t)c * 16);
    }
    CP_COMMIT();
}

// acc += A(32x128) @ B(128x32)^T for this warp's 32x32 tile.
__device__ __forceinline__ void gemm_into(float (&acc)[2][4][4], uint32_t aBase, uint32_t bBase) {
#pragma unroll
    for (int kc = 0; kc < 4; kc++) {              // k32 chunks
        uint32_t A[2][2][4];
        uint32_t Bf[4][4];
#pragma unroll
        for (int mt = 0; mt < 2; mt++) {
            ldsm4(A[mt][0], aBase + mt * 4352 + kc * 64);        // k lo16
            ldsm4(A[mt][1], aBase + mt * 4352 + kc * 64 + 32);   // k hi16
        }
#pragma unroll
        for (int nt = 0; nt < 4; nt++)
            ldsm4(Bf[nt], bBase + nt * 2176 + kc * 64);          // n8 x k32
#pragma unroll
        for (int mt = 0; mt < 2; mt++)
#pragma unroll
            for (int nt = 0; nt < 4; nt++) {
                mma_16816(acc[mt][nt], A[mt][0], Bf[nt][0], Bf[nt][1]);
                mma_16816(acc[mt][nt], A[mt][1], Bf[nt][2], Bf[nt][3]);
            }
    }
}

#define ZERO_ACC() do { _Pragma("unroll") \
    for (int mt = 0; mt < 2; mt++) _Pragma("unroll") \
        for (int nt = 0; nt < 4; nt++) \
            acc[mt][nt][0] = acc[mt][nt][1] = acc[mt][nt][2] = acc[mt][nt][3] = 0.f; } while (0)

__global__ void __launch_bounds__(256, 2)
gru_gemm_kernel(const float* __restrict__ atom_state,
                const float* __restrict__ bias,
                float* __restrict__ out)
{
    extern __shared__ char smem[];
    const uint32_t sb = smem_u32(smem);
    const int tid  = threadIdx.x;
    const int wid  = tid >> 5;
    const int lane = tid & 31;
    const int wr   = wid & 1;          // warp row group (2 x 32 rows)
    const int wc   = wid >> 1;         // warp col group (4 x 32 cols)
    const int row0 = blockIdx.x * 64;

    float* bias_s = reinterpret_cast<float*>(smem + OFF_BIAS);

    // ---- async prefetches: B(p0) [g0], agg A-tile [g1], B(p1) [g2] ----
    prefetch_B(sb + OFF_B0, 0, tid);
    prefetch_A_agg(sb + OFF_AG, g_agg + (size_t)row0 * 128, tid);
    prefetch_B(sb + OFF_B1, 1, tid);

    // ---- issue h LDGs now; convert+store after phase 0 (hidden latency) ----
    float4 hv[8];
    {
        const float4* hp = reinterpret_cast<const float4*>(atom_state + (size_t)row0 * 128);
#pragma unroll
        for (int k = 0; k < 8; k++)
            hv[k] = hp[tid + k * 256];            // 2048 f4
    }

    // ---- stage bias ----
    for (int i = tid; i < 768; i += 256) bias_s[i] = bias[i];

    // ---- per-lane ldmatrix address patterns ----
    const int g4  = lane >> 2;            // fragment row within 8
    const int tig = lane & 3;             // thread-in-group (col pair)
    const int t   = lane >> 3;            // ldmatrix tile index
    const int r8  = lane & 7;             // row within tile
    const uint32_t aoff = (uint32_t)(((wr * 32 + (t & 1) * 8 + r8) * 136 + (t >> 1) * 8) * 2);
    const uint32_t boff = (uint32_t)(((wc * 32 + r8) * 136 + t * 8) * 2);
    const uint32_t aAg = sb + OFF_AG + aoff;
    const uint32_t aAh = sb + OFF_AH + aoff;
    const uint32_t bB0 = sb + OFF_B0 + boff;
    const uint32_t bB1 = sb + OFF_B1 + boff;

    float acc[2][4][4];
    __half2 zpk[2][4][2];
    __half2 rpk[2][4][2];

    // ================= phase 0: acc = agg @ Wx_z =================
    CP_WAIT(1);                           // B0 + agg done (B1 still in flight)
    __syncthreads();
    ZERO_ACC();
    gemm_into(acc, aAg, bB0);
    __syncthreads();                      // done reading B0

    // ---- now convert+store the h tile (LDGs long done), then prefetch p2 ----
#pragma unroll
    for (int k = 0; k < 8; k++) {
        int idx = tid + k * 256;
        int row = idx >> 5;
        int f4  = idx & 31;
        union { __half2 h2[2]; uint2 u; } cv;
        cv.h2[0] = __floats2half2_rn(hv[k].x, hv[k].y);
        cv.h2[1] = __floats2half2_rn(hv[k].z, hv[k].w);
        *reinterpret_cast<uint2*>(smem + OFF_AH + row * 272 + f4 * 8) = cv.u;
    }
    prefetch_B(sb + OFF_B0, 2, tid);

    // ================= phase 1: acc += h @ Wh_z  -> z =================
    CP_WAIT(1);
    __syncthreads();                      // B1 + AH visible
    gemm_into(acc, aAh, bB1);
#pragma unroll
    for (int mt = 0; mt < 2; mt++)
#pragma unroll
        for (int nt = 0; nt < 4; nt++) {
            int colb = wc * 32 + nt * 8 + tig * 2;
            float b0 = bias_s[colb]     + bias_s[384 + colb];
            float b1 = bias_s[colb + 1] + bias_s[384 + colb + 1];
            zpk[mt][nt][0] = __floats2half2_rn(sigf(acc[mt][nt][0] + b0), sigf(acc[mt][nt][1] + b1));
            zpk[mt][nt][1] = __floats2half2_rn(sigf(acc[mt][nt][2] + b0), sigf(acc[mt][nt][3] + b1));
        }
    __syncthreads();
    prefetch_B(sb + OFF_B1, 3, tid);

    // ================= phase 2: acc = agg @ Wx_r =================
    CP_WAIT(1);
    __syncthreads();
    ZERO_ACC();
    gemm_into(acc, aAg, bB0);
    __syncthreads();
    prefetch_B(sb + OFF_B0, 4, tid);

    // ================= phase 3: acc += h @ Wh_r  -> r =================
    CP_WAIT(1);
    __syncthreads();
    gemm_into(acc, aAh, bB1);
#pragma unroll
    for (int mt = 0; mt < 2; mt++)
#pragma unroll
        for (int nt = 0; nt < 4; nt++) {
            int colb = wc * 32 + nt * 8 + tig * 2;
            float b0 = bias_s[128 + colb]     + bias_s[384 + 128 + colb];
            float b1 = bias_s[128 + colb + 1] + bias_s[384 + 128 + colb + 1];
            rpk[mt][nt][0] = __floats2half2_rn(sigf(acc[mt][nt][0] + b0), sigf(acc[mt][nt][1] + b1));
            rpk[mt][nt][1] = __floats2half2_rn(sigf(acc[mt][nt][2] + b0), sigf(acc[mt][nt][3] + b1));
        }
    __syncthreads();
    prefetch_B(sb + OFF_B1, 5, tid);

    // ================= phase 4: acc = h @ Wh_h ; r := r*(acc+b) =================
    CP_WAIT(1);
    __syncthreads();
    ZERO_ACC();
    gemm_into(acc, aAh, bB0);
#pragma unroll
    for (int mt = 0; mt < 2; mt++)
#pragma unroll
        for (int nt = 0; nt < 4; nt++) {
            int colb = wc * 32 + nt * 8 + tig * 2;
            float b0 = bias_s[384 + 256 + colb];
            float b1 = bias_s[384 + 256 + colb + 1];
            float2 ra = __half22float2(rpk[mt][nt][0]);
            float2 rb = __half22float2(rpk[mt][nt][1]);
            rpk[mt][nt][0] = __floats2half2_rn(ra.x * (acc[mt][nt][0] + b0), ra.y * (acc[mt][nt][1] + b1));
            rpk[mt][nt][1] = __floats2half2_rn(rb.x * (acc[mt][nt][2] + b0), rb.y * (acc[mt][nt][3] + b1));
        }
    // no sync needed: phase 5's buffer (B1) was prefetched before phase 4

    // ================= phase 5: acc = agg @ Wx_h ; final epilogue =================
    CP_WAIT(0);
    __syncthreads();
    ZERO_ACC();
    gemm_into(acc, aAg, bB1);

#pragma unroll
    for (int mt = 0; mt < 2; mt++) {
        const int lrow_a = wr * 32 + mt * 16 + g4;
        const int lrow_b = lrow_a + 8;
#pragma unroll
        for (int nt = 0; nt < 4; nt++) {
            int colb = wc * 32 + nt * 8 + tig * 2;
            float b0 = bias_s[256 + colb];
            float b1 = bias_s[256 + colb + 1];
            float2 tA = __half22float2(rpk[mt][nt][0]);
            float2 tB = __half22float2(rpk[mt][nt][1]);
            float2 zA = __half22float2(zpk[mt][nt][0]);
            float2 zB = __half22float2(zpk[mt][nt][1]);
            float2 hA = __half22float2(*reinterpret_cast<const __half2*>(
                smem + OFF_AH + lrow_a * 272 + colb * 2));
            float2 hB = __half22float2(*reinterpret_cast<const __half2*>(
                smem + OFF_AH + lrow_b * 272 + colb * 2));

            float hh0 = tanh_ap(acc[mt][nt][0] + b0 + tA.x);
            float hh1 = tanh_ap(acc[mt][nt][1] + b1 + tA.y);
            float hh2 = tanh_ap(acc[mt][nt][2] + b0 + tB.x);
            float hh3 = tanh_ap(acc[mt][nt][3] + b1 + tB.y);

            float2 oA = make_float2(zA.x * hA.x + (1.f - zA.x) * hh0,
                                    zA.y * hA.y + (1.f - zA.y) * hh1);
            float2 oB = make_float2(zB.x * hB.x + (1.f - zB.x) * hh2,
                                    zB.y * hB.y + (1.f - zB.y) * hh3);
            *reinterpret_cast<float2*>(out + (size_t)(row0 + lrow_a) * 128 + colb) = oA;
            *reinterpret_cast<float2*>(out + (size_t)(row0 + lrow_b) * 128 + colb) = oB;
        }
    }
}

// ================================================================================
// Launch
// ================================================================================
extern "C" void kernel_launch(void* const* d_in, const int* in_sizes, int n_in,
                              void* d_out, int out_size) {
    const float* atom_state = (const float*)d_in[0];
    const float* messages   = (const float*)d_in[1];
    const int*   conn       = (const int*)d_in[2];
    const float* kern       = (const float*)d_in[3];
    const float* rker       = (const float*)d_in[4];
    const float* bias       = (const float*)d_in[5];
    float* out = (float*)d_out;

    static bool attr_set = false;
    if (!attr_set) {
        cudaFuncSetAttribute(gru_gemm_kernel, cudaFuncAttributeMaxDynamicSharedMemorySize, SMEM_TOTAL);
        attr_set = true;
    }

    prep_w_kernel<<<(2 * 384 * 128 + 255) / 256, 256>>>(kern, rker);
    zero_agg_kernel<<<2048, 256>>>();
    scatter_kernel<<<(NEDGE / 2 * 32) / 256, 256>>>(messages, conn);
    gru_gemm_kernel<<<ROWS_TOTAL / 64, 256, SMEM_TOTAL>>>(atom_state, bias, out);
}